// round 1
// baseline (speedup 1.0000x reference)
#include <cuda_runtime.h>

#define N_NODES 50000
#define N_EDGES 800000
#define IN_CH   128
#define HID     64
#define HID2    32

// ---------------- scratch (device globals; no allocations allowed) ----------
__device__ float g_deg [N_NODES];
__device__ float g_dinv[N_NODES];
__device__ int   g_rows[N_EDGES];
__device__ int   g_cols[N_EDGES];
__device__ int   g_is64;
__device__ float g_h1  [N_NODES * HID];   // x @ W1
__device__ float g_agg1[N_NODES * HID];   // aggregated layer-1 messages
__device__ float g_h2  [N_NODES * HID2];  // relu(bn(agg1+b1)) @ W2
__device__ float g_agg2[N_NODES * HID2];
__device__ float g_s1[HID],  g_t1[HID];   // folded bias+BN affine, layer 1
__device__ float g_s2[HID2], g_t2[HID2];  // folded bias+BN affine, layer 2

// ---------------- dtype detection for edge_index ----------------------------
// If edge_index is int64 (values in [0, 50000)), the high 32-bit word of every
// element is 0. If it is int32, the words at odd positions are edge indices
// (almost never 0). Deterministic: same input -> same flag.
__global__ void detect_kernel(const unsigned int* __restrict__ w) {
    __shared__ int cnt;
    if (threadIdx.x == 0) cnt = 0;
    __syncthreads();
    int local = 0;
    for (int i = threadIdx.x; i < 2048; i += 256)
        if (w[2 * i + 1] != 0u) local++;
    atomicAdd(&cnt, local);
    __syncthreads();
    if (threadIdx.x == 0) g_is64 = (cnt < 100) ? 1 : 0;
}

// ---------------- init: degrees (self loop = 1) + folded BN affines ---------
__global__ void init_kernel(const float* __restrict__ b1, const float* __restrict__ rm1,
                            const float* __restrict__ rv1, const float* __restrict__ g1,
                            const float* __restrict__ be1,
                            const float* __restrict__ b2, const float* __restrict__ rm2,
                            const float* __restrict__ rv2, const float* __restrict__ g2,
                            const float* __restrict__ be2) {
    int i = blockIdx.x * blockDim.x + threadIdx.x;
    if (i < N_NODES) g_deg[i] = 1.0f;   // self loop
    if (blockIdx.x == 0) {
        int t = threadIdx.x;
        if (t < HID) {
            float s = g1[t] * rsqrtf(rv1[t] + 1e-5f);
            g_s1[t] = s;
            g_t1[t] = (b1[t] - rm1[t]) * s + be1[t];
        } else if (t < HID + HID2) {
            int c = t - HID;
            float s = g2[c] * rsqrtf(rv2[c] + 1e-5f);
            g_s2[c] = s;
            g_t2[c] = (b2[c] - rm2[c]) * s + be2[c];
        }
    }
}

// ---------------- convert edges to int32 + accumulate degree ----------------
__global__ void convert_kernel(const void* __restrict__ ei) {
    int e = blockIdx.x * blockDim.x + threadIdx.x;
    if (e >= N_EDGES) return;
    int r, c;
    if (g_is64) {
        const long long* p = (const long long*)ei;
        r = (int)p[e];
        c = (int)p[N_EDGES + e];
    } else {
        const int* p = (const int*)ei;
        r = p[e];
        c = p[N_EDGES + e];
    }
    g_rows[e] = r;
    g_cols[e] = c;
    atomicAdd(&g_deg[c], 1.0f);
}

__global__ void dinv_kernel() {
    int i = blockIdx.x * blockDim.x + threadIdx.x;
    if (i < N_NODES) g_dinv[i] = rsqrtf(g_deg[i]);   // deg >= 1 always
}

// ---------------- GEMM1: h1 = x @ W1; agg1 = h1 * dinv^2 (self loop) --------
// Tiles: BM=64, BN=64, BK=32; 256 threads, 4x4 microtile per thread.
__global__ __launch_bounds__(256) void gemm1_kernel(const float* __restrict__ x,
                                                    const float* __restrict__ W1) {
    __shared__ float xst[32][64];   // [k][m] (transposed for float4 reads)
    __shared__ float ws [32][64];   // [k][n]
    int tid = threadIdx.x;
    int tx = tid & 15, ty = tid >> 4;
    int m0 = blockIdx.x * 64;
    float acc[4][4] = {};

    for (int kb = 0; kb < 4; kb++) {
#pragma unroll
        for (int q = 0; q < 2; q++) {          // load x tile (64 rows x 32 k)
            int id = tid + q * 256;            // 0..511 float4s
            int ml = id >> 3;                  // row in tile (8 float4/row)
            int k4 = id & 7;
            int row = m0 + ml;
            float4 v = make_float4(0.f, 0.f, 0.f, 0.f);
            if (row < N_NODES)
                v = *(const float4*)&x[row * IN_CH + kb * 32 + k4 * 4];
            xst[k4 * 4 + 0][ml] = v.x;
            xst[k4 * 4 + 1][ml] = v.y;
            xst[k4 * 4 + 2][ml] = v.z;
            xst[k4 * 4 + 3][ml] = v.w;
        }
#pragma unroll
        for (int q = 0; q < 2; q++) {          // load W1 tile (32 k x 64 n)
            int id = tid + q * 256;
            int kl = id >> 4;                  // 0..31
            int n4 = id & 15;                  // 16 float4 per row
            *(float4*)&ws[kl][n4 * 4] =
                *(const float4*)&W1[(kb * 32 + kl) * HID + n4 * 4];
        }
        __syncthreads();
#pragma unroll
        for (int kk = 0; kk < 32; kk++) {
            float av[4], bv[4];
            *(float4*)av = *(const float4*)&xst[kk][ty * 4];
            *(float4*)bv = *(const float4*)&ws[kk][tx * 4];
#pragma unroll
            for (int i = 0; i < 4; i++)
#pragma unroll
                for (int j = 0; j < 4; j++)
                    acc[i][j] += av[i] * bv[j];
        }
        __syncthreads();
    }
#pragma unroll
    for (int i = 0; i < 4; i++) {
        int row = m0 + ty * 4 + i;
        if (row < N_NODES) {
            float d = g_dinv[row];
            float d2 = d * d;
            float4 hv = make_float4(acc[i][0], acc[i][1], acc[i][2], acc[i][3]);
            *(float4*)&g_h1[row * HID + tx * 4] = hv;
            float4 av = make_float4(hv.x * d2, hv.y * d2, hv.z * d2, hv.w * d2);
            *(float4*)&g_agg1[row * HID + tx * 4] = av;
        }
    }
}

// ---------------- vector reduction helper ------------------------------------
__device__ __forceinline__ void red_add_v4(float4* dst, float a, float b, float c, float d) {
    asm volatile("red.global.add.v4.f32 [%0], {%1, %2, %3, %4};"
                 :: "l"(dst), "f"(a), "f"(b), "f"(c), "f"(d)
                 : "memory");
}

// ---------------- scatter 1: 16 threads (float4 lanes) per edge -------------
__global__ __launch_bounds__(256) void scatter1_kernel() {
    int gid = blockIdx.x * 256 + threadIdx.x;   // exactly E*16 threads
    int e = gid >> 4;
    int part = gid & 15;
    int r = g_rows[e];
    int c = g_cols[e];
    float w = g_dinv[r] * g_dinv[c];
    float4 v = *((const float4*)g_h1 + r * 16 + part);
    red_add_v4((float4*)g_agg1 + c * 16 + part, v.x * w, v.y * w, v.z * w, v.w * w);
}

// ---------------- GEMM2: h2 = relu(agg1*s1+t1) @ W2; agg2 = h2*dinv^2 -------
// BM=64, BN=32, BK=64 (single K pass); 256 threads, 4x2 microtile.
__global__ __launch_bounds__(256) void gemm2_kernel(const float* __restrict__ W2) {
    __shared__ float ast[64][64];  // [k][m], affine+relu applied on load
    __shared__ float w2s[64][32];  // [k][n]
    int tid = threadIdx.x;
    int tx = tid & 15, ty = tid >> 4;
    int m0 = blockIdx.x * 64;

#pragma unroll
    for (int q = 0; q < 4; q++) {              // 1024 float4 loads of agg1
        int id = tid + q * 256;
        int ml = id >> 4;                      // row 0..63
        int k4 = id & 15;                      // 16 float4 per row
        int row = m0 + ml;
        float v[4] = {0.f, 0.f, 0.f, 0.f};
        if (row < N_NODES)
            *(float4*)v = *(const float4*)&g_agg1[row * HID + k4 * 4];
#pragma unroll
        for (int i = 0; i < 4; i++) {
            int k = k4 * 4 + i;
            float z = fmaxf(v[i] * g_s1[k] + g_t1[k], 0.0f);
            ast[k][ml] = (row < N_NODES) ? z : 0.0f;
        }
    }
#pragma unroll
    for (int q = 0; q < 2; q++) {              // W2: 64x32
        int id = tid + q * 256;
        int kl = id >> 3;                      // 0..63
        int n4 = id & 7;                       // 8 float4 per row
        *(float4*)&w2s[kl][n4 * 4] = *(const float4*)&W2[kl * HID2 + n4 * 4];
    }
    __syncthreads();

    float acc[4][2] = {};
#pragma unroll
    for (int kk = 0; kk < 64; kk++) {
        float av[4], bv[2];
        *(float4*)av = *(const float4*)&ast[kk][ty * 4];
        *(float2*)bv = *(const float2*)&w2s[kk][tx * 2];
#pragma unroll
        for (int i = 0; i < 4; i++) {
            acc[i][0] += av[i] * bv[0];
            acc[i][1] += av[i] * bv[1];
        }
    }
#pragma unroll
    for (int i = 0; i < 4; i++) {
        int row = m0 + ty * 4 + i;
        if (row < N_NODES) {
            float d = g_dinv[row];
            float d2 = d * d;
            *(float2*)&g_h2[row * HID2 + tx * 2]   = make_float2(acc[i][0], acc[i][1]);
            *(float2*)&g_agg2[row * HID2 + tx * 2] = make_float2(acc[i][0] * d2, acc[i][1] * d2);
        }
    }
}

// ---------------- scatter 2: 8 threads (float4 lanes) per edge --------------
__global__ __launch_bounds__(256) void scatter2_kernel() {
    int gid = blockIdx.x * 256 + threadIdx.x;   // exactly E*8 threads
    int e = gid >> 3;
    int part = gid & 7;
    int r = g_rows[e];
    int c = g_cols[e];
    float w = g_dinv[r] * g_dinv[c];
    float4 v = *((const float4*)g_h2 + r * 8 + part);
    red_add_v4((float4*)g_agg2 + c * 8 + part, v.x * w, v.y * w, v.z * w, v.w * w);
}

// ---------------- final: out = relu(agg2*s2+t2) @ fcW^T + fcb ---------------
__global__ __launch_bounds__(256) void final_kernel(const float* __restrict__ fcW,
                                                    const float* __restrict__ fcb,
                                                    float* __restrict__ out) {
    int gid = blockIdx.x * 256 + threadIdx.x;
    int node = gid >> 5;
    int lane = gid & 31;
    if (node >= N_NODES) return;
    float v = g_agg2[node * HID2 + lane];
    v = fmaxf(v * g_s2[lane] + g_t2[lane], 0.0f) * fcW[lane];
#pragma unroll
    for (int o = 16; o > 0; o >>= 1)
        v += __shfl_xor_sync(0xffffffffu, v, o);
    if (lane == 0) out[node] = v + fcb[0];
}

// ---------------- launch -----------------------------------------------------
extern "C" void kernel_launch(void* const* d_in, const int* in_sizes, int n_in,
                              void* d_out, int out_size) {
    const float* x   = (const float*)d_in[0];
    const void*  ei  = d_in[1];
    const float* W1  = (const float*)d_in[2];
    const float* b1  = (const float*)d_in[3];
    const float* W2  = (const float*)d_in[4];
    const float* b2  = (const float*)d_in[5];
    const float* fcW = (const float*)d_in[6];
    const float* fcb = (const float*)d_in[7];
    const float* g1  = (const float*)d_in[8];
    const float* be1 = (const float*)d_in[9];
    const float* rm1 = (const float*)d_in[10];
    const float* rv1 = (const float*)d_in[11];
    const float* g2  = (const float*)d_in[12];
    const float* be2 = (const float*)d_in[13];
    const float* rm2 = (const float*)d_in[14];
    const float* rv2 = (const float*)d_in[15];
    float* out = (float*)d_out;

    detect_kernel<<<1, 256>>>((const unsigned int*)ei);
    init_kernel<<<(N_NODES + 255) / 256, 256>>>(b1, rm1, rv1, g1, be1,
                                                b2, rm2, rv2, g2, be2);
    convert_kernel<<<(N_EDGES + 255) / 256, 256>>>(ei);
    dinv_kernel<<<(N_NODES + 255) / 256, 256>>>();
    gemm1_kernel<<<(N_NODES + 63) / 64, 256>>>(x, W1);
    scatter1_kernel<<<N_EDGES * 16 / 256, 256>>>();
    gemm2_kernel<<<(N_NODES + 63) / 64, 256>>>(W2);
    scatter2_kernel<<<N_EDGES * 8 / 256, 256>>>();
    final_kernel<<<(N_NODES * 32 + 255) / 256, 256>>>(fcW, fcb, out);
}

// round 2
// speedup vs baseline: 1.2254x; 1.2254x over previous
#include <cuda_runtime.h>

#define N_NODES 50000
#define N_EDGES 800000
#define IN_CH   128
#define HID     64
#define HID2    32
#define NB1     ((N_NODES + 511) / 512)   // scan blocks = 98

// ---------------- scratch (device globals; no allocations allowed) ----------
__device__ int   g_cnt   [N_NODES];       // neighbor count (excl. self loop)
__device__ int   g_lex   [N_NODES];       // local exclusive scan
__device__ int   g_bsum  [NB1];
__device__ int   g_boff  [NB1];
__device__ int   g_start [N_NODES];       // CSR row start
__device__ int   g_cursor[N_NODES];
__device__ int   g_csr   [N_EDGES];       // source node per CSR slot
__device__ float g_dinv  [N_NODES];
__device__ int   g_rows  [N_EDGES];
__device__ int   g_cols  [N_EDGES];
__device__ int   g_is64;
__device__ float g_h1m [N_NODES * HID];   // (x @ W1) * dinv   (message-ready)
__device__ float g_agg1[N_NODES * HID];
__device__ float g_h2m [N_NODES * HID2];  // h2 * dinv
__device__ float g_s1[HID],  g_t1[HID];   // folded bias+BN affine, layer 1
__device__ float g_s2[HID2], g_t2[HID2];  // folded bias+BN affine, layer 2

// ---------------- dtype detection for edge_index ----------------------------
// int64 indices in [0,50000) have zero high words; int32 data at those word
// positions is (almost) never all zero. Deterministic per input.
__global__ void detect_kernel(const unsigned int* __restrict__ w) {
    __shared__ int cnt;
    if (threadIdx.x == 0) cnt = 0;
    __syncthreads();
    int local = 0;
    for (int i = threadIdx.x; i < 2048; i += 256)
        if (w[2 * i + 1] != 0u) local++;
    atomicAdd(&cnt, local);
    __syncthreads();
    if (threadIdx.x == 0) g_is64 = (cnt < 100) ? 1 : 0;
}

// ---------------- init: zero counts + folded BN affines ---------------------
__global__ void init_kernel(const float* __restrict__ b1, const float* __restrict__ rm1,
                            const float* __restrict__ rv1, const float* __restrict__ g1,
                            const float* __restrict__ be1,
                            const float* __restrict__ b2, const float* __restrict__ rm2,
                            const float* __restrict__ rv2, const float* __restrict__ g2,
                            const float* __restrict__ be2) {
    int i = blockIdx.x * blockDim.x + threadIdx.x;
    if (i < N_NODES) g_cnt[i] = 0;
    if (blockIdx.x == 0) {
        int t = threadIdx.x;
        if (t < HID) {
            float s = g1[t] * rsqrtf(rv1[t] + 1e-5f);
            g_s1[t] = s;
            g_t1[t] = (b1[t] - rm1[t]) * s + be1[t];
        } else if (t < HID + HID2) {
            int c = t - HID;
            float s = g2[c] * rsqrtf(rv2[c] + 1e-5f);
            g_s2[c] = s;
            g_t2[c] = (b2[c] - rm2[c]) * s + be2[c];
        }
    }
}

// ---------------- convert edges to int32 + histogram ------------------------
__global__ void convert_kernel(const void* __restrict__ ei) {
    int e = blockIdx.x * blockDim.x + threadIdx.x;
    if (e >= N_EDGES) return;
    int r, c;
    if (g_is64) {
        const long long* p = (const long long*)ei;
        r = (int)p[e];
        c = (int)p[N_EDGES + e];
    } else {
        const int* p = (const int*)ei;
        r = p[e];
        c = p[N_EDGES + e];
    }
    g_rows[e] = r;
    g_cols[e] = c;
    atomicAdd(&g_cnt[c], 1);
}

// ---------------- 3-kernel exclusive scan over g_cnt ------------------------
__global__ __launch_bounds__(512) void scan1_kernel() {
    __shared__ int s[512];
    int t = threadIdx.x;
    int i = blockIdx.x * 512 + t;
    int v = (i < N_NODES) ? g_cnt[i] : 0;
    s[t] = v;
    __syncthreads();
#pragma unroll
    for (int off = 1; off < 512; off <<= 1) {
        int u = (t >= off) ? s[t - off] : 0;
        __syncthreads();
        s[t] += u;
        __syncthreads();
    }
    if (i < N_NODES) g_lex[i] = s[t] - v;          // exclusive
    if (t == 511) g_bsum[blockIdx.x] = s[511];
}

__global__ void scan2_kernel() {
    __shared__ int s[128];
    int t = threadIdx.x;
    int v = (t < NB1) ? g_bsum[t] : 0;
    s[t] = v;
    __syncthreads();
#pragma unroll
    for (int off = 1; off < 128; off <<= 1) {
        int u = (t >= off) ? s[t - off] : 0;
        __syncthreads();
        s[t] += u;
        __syncthreads();
    }
    if (t < NB1) g_boff[t] = s[t] - v;             // exclusive
}

__global__ void scan3_kernel() {
    int i = blockIdx.x * blockDim.x + threadIdx.x;
    if (i >= N_NODES) return;
    int st = g_lex[i] + g_boff[i >> 9];
    g_start[i]  = st;
    g_cursor[i] = st;
    g_dinv[i]   = rsqrtf(1.0f + (float)g_cnt[i]);  // +1 self loop
}

// ---------------- CSR build --------------------------------------------------
__global__ void build_kernel() {
    int e = blockIdx.x * blockDim.x + threadIdx.x;
    if (e >= N_EDGES) return;
    int c = g_cols[e];
    int pos = atomicAdd(&g_cursor[c], 1);
    g_csr[pos] = g_rows[e];
}

// ---------------- GEMM1: h1m = (x @ W1) * dinv ------------------------------
// Tiles: BM=64, BN=64, BK=32; 256 threads, 4x4 microtile per thread.
__global__ __launch_bounds__(256) void gemm1_kernel(const float* __restrict__ x,
                                                    const float* __restrict__ W1) {
    __shared__ float xst[32][64];   // [k][m]
    __shared__ float ws [32][64];   // [k][n]
    int tid = threadIdx.x;
    int tx = tid & 15, ty = tid >> 4;
    int m0 = blockIdx.x * 64;
    float acc[4][4] = {};

    for (int kb = 0; kb < 4; kb++) {
#pragma unroll
        for (int q = 0; q < 2; q++) {
            int id = tid + q * 256;
            int ml = id >> 3;
            int k4 = id & 7;
            int row = m0 + ml;
            float4 v = make_float4(0.f, 0.f, 0.f, 0.f);
            if (row < N_NODES)
                v = *(const float4*)&x[row * IN_CH + kb * 32 + k4 * 4];
            xst[k4 * 4 + 0][ml] = v.x;
            xst[k4 * 4 + 1][ml] = v.y;
            xst[k4 * 4 + 2][ml] = v.z;
            xst[k4 * 4 + 3][ml] = v.w;
        }
#pragma unroll
        for (int q = 0; q < 2; q++) {
            int id = tid + q * 256;
            int kl = id >> 4;
            int n4 = id & 15;
            *(float4*)&ws[kl][n4 * 4] =
                *(const float4*)&W1[(kb * 32 + kl) * HID + n4 * 4];
        }
        __syncthreads();
#pragma unroll
        for (int kk = 0; kk < 32; kk++) {
            float av[4], bv[4];
            *(float4*)av = *(const float4*)&xst[kk][ty * 4];
            *(float4*)bv = *(const float4*)&ws[kk][tx * 4];
#pragma unroll
            for (int i = 0; i < 4; i++)
#pragma unroll
                for (int j = 0; j < 4; j++)
                    acc[i][j] += av[i] * bv[j];
        }
        __syncthreads();
    }
#pragma unroll
    for (int i = 0; i < 4; i++) {
        int row = m0 + ty * 4 + i;
        if (row < N_NODES) {
            float d = g_dinv[row];
            *(float4*)&g_h1m[row * HID + tx * 4] =
                make_float4(acc[i][0] * d, acc[i][1] * d, acc[i][2] * d, acc[i][3] * d);
        }
    }
}

// ---------------- aggregation layer 1: gather over CSR ----------------------
// One warp per node; each lane owns 2 channels (float2). Self loop = init.
__global__ __launch_bounds__(256) void agg1_kernel() {
    int warp = (blockIdx.x * 256 + threadIdx.x) >> 5;
    int lane = threadIdx.x & 31;
    if (warp >= N_NODES) return;
    int n = warp;
    int start = g_start[n];
    int deg   = g_cnt[n];
    const float2* __restrict__ h = (const float2*)g_h1m;
    float2 acc = h[n * 32 + lane];               // self message (h*dinv)
    int j = 0;
    for (; j + 4 <= deg; j += 4) {
        int r0 = g_csr[start + j];
        int r1 = g_csr[start + j + 1];
        int r2 = g_csr[start + j + 2];
        int r3 = g_csr[start + j + 3];
        float2 v0 = h[r0 * 32 + lane];
        float2 v1 = h[r1 * 32 + lane];
        float2 v2 = h[r2 * 32 + lane];
        float2 v3 = h[r3 * 32 + lane];
        acc.x += (v0.x + v1.x) + (v2.x + v3.x);
        acc.y += (v0.y + v1.y) + (v2.y + v3.y);
    }
    for (; j < deg; j++) {
        int r = g_csr[start + j];
        float2 v = h[r * 32 + lane];
        acc.x += v.x;
        acc.y += v.y;
    }
    float d = g_dinv[n];
    ((float2*)g_agg1)[n * 32 + lane] = make_float2(acc.x * d, acc.y * d);
}

// ---------------- GEMM2: h2m = (relu(agg1*s1+t1) @ W2) * dinv ---------------
__global__ __launch_bounds__(256) void gemm2_kernel(const float* __restrict__ W2) {
    __shared__ float ast[64][64];  // [k][m]
    __shared__ float w2s[64][32];  // [k][n]
    int tid = threadIdx.x;
    int tx = tid & 15, ty = tid >> 4;
    int m0 = blockIdx.x * 64;

#pragma unroll
    for (int q = 0; q < 4; q++) {
        int id = tid + q * 256;
        int ml = id >> 4;
        int k4 = id & 15;
        int row = m0 + ml;
        float v[4] = {0.f, 0.f, 0.f, 0.f};
        if (row < N_NODES)
            *(float4*)v = *(const float4*)&g_agg1[row * HID + k4 * 4];
#pragma unroll
        for (int i = 0; i < 4; i++) {
            int k = k4 * 4 + i;
            float z = fmaxf(v[i] * g_s1[k] + g_t1[k], 0.0f);
            ast[k][ml] = (row < N_NODES) ? z : 0.0f;
        }
    }
#pragma unroll
    for (int q = 0; q < 2; q++) {
        int id = tid + q * 256;
        int kl = id >> 3;
        int n4 = id & 7;
        *(float4*)&w2s[kl][n4 * 4] = *(const float4*)&W2[kl * HID2 + n4 * 4];
    }
    __syncthreads();

    float acc[4][2] = {};
#pragma unroll
    for (int kk = 0; kk < 64; kk++) {
        float av[4], bv[2];
        *(float4*)av = *(const float4*)&ast[kk][ty * 4];
        *(float2*)bv = *(const float2*)&w2s[kk][tx * 2];
#pragma unroll
        for (int i = 0; i < 4; i++) {
            acc[i][0] += av[i] * bv[0];
            acc[i][1] += av[i] * bv[1];
        }
    }
#pragma unroll
    for (int i = 0; i < 4; i++) {
        int row = m0 + ty * 4 + i;
        if (row < N_NODES) {
            float d = g_dinv[row];
            *(float2*)&g_h2m[row * HID2 + tx * 2] =
                make_float2(acc[i][0] * d, acc[i][1] * d);
        }
    }
}

// ---------------- aggregation layer 2 + BN/ReLU + fc, fused -----------------
// One warp per node; lane owns 1 channel of 32; warp-reduce the fc dot.
__global__ __launch_bounds__(256) void agg2_final_kernel(const float* __restrict__ fcW,
                                                         const float* __restrict__ fcb,
                                                         float* __restrict__ out) {
    int warp = (blockIdx.x * 256 + threadIdx.x) >> 5;
    int lane = threadIdx.x & 31;
    if (warp >= N_NODES) return;
    int n = warp;
    int start = g_start[n];
    int deg   = g_cnt[n];
    const float* __restrict__ h = g_h2m;
    float acc = h[n * 32 + lane];                 // self message
    int j = 0;
    for (; j + 4 <= deg; j += 4) {
        int r0 = g_csr[start + j];
        int r1 = g_csr[start + j + 1];
        int r2 = g_csr[start + j + 2];
        int r3 = g_csr[start + j + 3];
        acc += (h[r0 * 32 + lane] + h[r1 * 32 + lane]) +
               (h[r2 * 32 + lane] + h[r3 * 32 + lane]);
    }
    for (; j < deg; j++)
        acc += h[g_csr[start + j] * 32 + lane];
    float agg = acc * g_dinv[n];
    float v = fmaxf(agg * g_s2[lane] + g_t2[lane], 0.0f) * fcW[lane];
#pragma unroll
    for (int o = 16; o > 0; o >>= 1)
        v += __shfl_xor_sync(0xffffffffu, v, o);
    if (lane == 0) out[n] = v + fcb[0];
}

// ---------------- launch -----------------------------------------------------
extern "C" void kernel_launch(void* const* d_in, const int* in_sizes, int n_in,
                              void* d_out, int out_size) {
    const float* x   = (const float*)d_in[0];
    const void*  ei  = d_in[1];
    const float* W1  = (const float*)d_in[2];
    const float* b1  = (const float*)d_in[3];
    const float* W2  = (const float*)d_in[4];
    const float* b2  = (const float*)d_in[5];
    const float* fcW = (const float*)d_in[6];
    const float* fcb = (const float*)d_in[7];
    const float* g1  = (const float*)d_in[8];
    const float* be1 = (const float*)d_in[9];
    const float* rm1 = (const float*)d_in[10];
    const float* rv1 = (const float*)d_in[11];
    const float* g2  = (const float*)d_in[12];
    const float* be2 = (const float*)d_in[13];
    const float* rm2 = (const float*)d_in[14];
    const float* rv2 = (const float*)d_in[15];
    float* out = (float*)d_out;

    detect_kernel<<<1, 256>>>((const unsigned int*)ei);
    init_kernel<<<(N_NODES + 255) / 256, 256>>>(b1, rm1, rv1, g1, be1,
                                                b2, rm2, rv2, g2, be2);
    convert_kernel<<<(N_EDGES + 255) / 256, 256>>>(ei);
    scan1_kernel<<<NB1, 512>>>();
    scan2_kernel<<<1, 128>>>();
    scan3_kernel<<<(N_NODES + 255) / 256, 256>>>();
    build_kernel<<<(N_EDGES + 255) / 256, 256>>>();
    gemm1_kernel<<<(N_NODES + 63) / 64, 256>>>(x, W1);
    agg1_kernel<<<(N_NODES * 32 + 255) / 256, 256>>>();
    gemm2_kernel<<<(N_NODES + 63) / 64, 256>>>(W2);
    agg2_final_kernel<<<(N_NODES * 32 + 255) / 256, 256>>>(fcW, fcb, out);
}